// round 1
// baseline (speedup 1.0000x reference)
#include <cuda_runtime.h>
#include <cuda_bf16.h>
#include <cstdint>

// Problem constants (fixed shapes for this problem instance)
#define B_IMGS   32
#define GRID     64
#define NCELL    (GRID * GRID)          // 4096
#define NDET     (NCELL * 3)            // 12288 detections per image
#define NSORT    16384                  // NDET padded to pow2
#define NCLS     80
#define D_PER_A  85
#define TOPK     1024
#define CNF_THR  0.5f
#define IOU_THR  0.4f
#define CLS_OFF  10000.0f
#define STRIDE_S 8.0f                   // HEIGHT/G = 512/64

// ---------------- device scratch (static, no runtime allocation) ----------------
__device__ float               g_det[(size_t)B_IMGS * NDET * 7];   // ~11 MB
__device__ unsigned long long  g_keys[(size_t)B_IMGS * NDET];      // ~3 MB
__device__ unsigned long long  g_top[(size_t)B_IMGS * TOPK];       // 256 KB

// order-preserving float->uint mapping (monotonic for all non-NaN floats incl -inf)
__device__ __forceinline__ unsigned int ord_f32(float f) {
    unsigned int u = __float_as_uint(f);
    return (u & 0x80000000u) ? ~u : (u | 0x80000000u);
}

// ================= Kernel 1: decode =================
// thread t in [0,12288): a = t/4096 (anchor), s = t%4096 (spatial, s = y*64+x)
// -> all 85 channel reads coalesced (contiguous s across the warp).
__global__ void __launch_bounds__(256) decode_kernel(const float* __restrict__ in) {
    const int b = blockIdx.y;
    const int t = blockIdx.x * blockDim.x + threadIdx.x;   // 0..12287
    const int a = t >> 12;         // anchor 0..2
    const int s = t & 4095;        // spatial: s = y*64 + x

    const float* p = in + ((size_t)b * 255 + (size_t)a * D_PER_A) * NCELL + s;

    const float t0 = p[0 * NCELL];
    const float t1 = p[1 * NCELL];
    const float t2 = p[2 * NCELL];
    const float t3 = p[3 * NCELL];
    const float t4 = p[4 * NCELL];

    // class max / argmax (first occurrence of max, matching jnp.argmax)
    float best = p[5 * NCELL];
    int   bi   = 0;
    #pragma unroll 4
    for (int d = 1; d < NCLS; ++d) {
        float v = p[(5 + d) * NCELL];
        if (v > best) { best = v; bi = d; }
    }

    const int y = s >> 6;
    const int x = s & 63;
    const int n = ((x << 6) + y) * 3 + a;   // detection index in reference order
    const int m = n & 4095;                 // offset index per reference's tiled meshgrid
    const float x_off = (float)(m >> 6);
    const float y_off = (float)(m & 63);

    const float cx = t0 + x_off;
    const float cy = t1 + y_off;
    const float hw = t2 * 0.5f;
    const float hh = t3 * 0.5f;
    const float conf = 1.0f / (1.0f + expf(-t4));

    float* dr = g_det + ((size_t)b * NDET + n) * 7;
    dr[0] = cx - hw;
    dr[1] = cy - hh;
    dr[2] = cx + hw;
    dr[3] = cy + hh;
    dr[4] = conf;
    dr[5] = best;
    dr[6] = (float)bi;

    // sort key: (ordered(score) << 32) | (0xFFFFFFFF - n)
    // score thresholded to -inf exactly like the reference
    const float score = (conf > CNF_THR) ? conf : (-__int_as_float(0x7f800000));
    const unsigned long long key =
        ((unsigned long long)ord_f32(score) << 32) | (unsigned long long)(0xFFFFFFFFu - (unsigned int)n);
    g_keys[(size_t)b * NDET + n] = key;
}

// ================= Kernel 2: per-image bitonic sort (descending) =================
// 1 CTA per image, 1024 threads, 16384 u64 keys in 128KB dynamic smem.
__global__ void __launch_bounds__(1024) sort_kernel() {
    extern __shared__ unsigned long long sk[];
    const int b   = blockIdx.x;
    const int tid = threadIdx.x;

    for (int i = tid; i < NSORT; i += 1024)
        sk[i] = (i < NDET) ? g_keys[(size_t)b * NDET + i] : 0ULL;
    __syncthreads();

    for (int k = 2; k <= NSORT; k <<= 1) {
        for (int j = k >> 1; j > 0; j >>= 1) {
            for (int i = tid; i < NSORT; i += 1024) {
                const int ixj = i ^ j;
                if (ixj > i) {
                    unsigned long long va = sk[i];
                    unsigned long long vb = sk[ixj];
                    const bool desc = ((i & k) == 0);
                    if (desc ? (va < vb) : (va > vb)) { sk[i] = vb; sk[ixj] = va; }
                }
            }
            __syncthreads();
        }
    }

    // top 1024 (descending, tie-broken by lower index) out
    g_top[(size_t)b * TOPK + tid] = sk[tid];
}

// ================= Kernel 3: NMS + output =================
// 1 CTA per image, 1024 threads.
// dyn smem layout:
//   float4 sbox[1024]   @0      (16384)
//   float  sarea[1024]  @16384  ( 4096)
//   uchar  svalid[1024] @20480  ( 1024)
//   uchar  skeep[1024]  @21504  ( 1024)
//   uint   smask[1024*32] @22528 (131072)   total = 153600
#define NMS_SMEM 153600
__global__ void __launch_bounds__(1024) nms_kernel(float* __restrict__ out) {
    extern __shared__ unsigned char smem[];
    float4*        sbox   = (float4*)(smem);
    float*         sarea  = (float*)(smem + 16384);
    unsigned char* svalid = (unsigned char*)(smem + 20480);
    unsigned char* skeep  = (unsigned char*)(smem + 21504);
    unsigned int*  smask  = (unsigned int*)(smem + 22528);

    const int b = blockIdx.x;
    const int i = threadIdx.x;

    const unsigned long long key = g_top[(size_t)b * TOPK + i];
    const unsigned int n = 0xFFFFFFFFu - (unsigned int)(key & 0xFFFFFFFFull);

    const float* dr = g_det + ((size_t)b * NDET + n) * 7;
    const float c0 = dr[0], c1 = dr[1], c2 = dr[2], c3 = dr[3];
    const float c4 = dr[4], c5 = dr[5], c6 = dr[6];

    const bool valid = (c4 > CNF_THR);
    const float sh = c6 * CLS_OFF;
    float4 bx;
    bx.x = c0 + sh; bx.y = c1 + sh; bx.z = c2 + sh; bx.w = c3 + sh;

    sbox[i]   = bx;
    sarea[i]  = (c2 - c0) * (c3 - c1);   // area invariant under shift
    svalid[i] = valid ? 1 : 0;
    __syncthreads();

    // build upper-triangular suppression mask row i (j > i only)
    const float myArea = sarea[i];
    unsigned int* myrow = smask + (size_t)i * 32;
    for (int w = 0; w < 32; ++w) {
        unsigned int bits = 0;
        const int j0 = w << 5;
        const int jlo = (j0 > i + 1) ? j0 : (i + 1);
        const int jhi = j0 + 32;
        for (int j = jlo; j < jhi; ++j) {
            const float4 ob = sbox[j];
            const float lx = fmaxf(bx.x, ob.x);
            const float ly = fmaxf(bx.y, ob.y);
            const float rx = fminf(bx.z, ob.z);
            const float ry = fminf(bx.w, ob.w);
            const float iw = fmaxf(rx - lx, 0.0f);
            const float ih = fmaxf(ry - ly, 0.0f);
            const float inter = iw * ih;
            const float iou = inter / (myArea + sarea[j] - inter + 1e-9f);
            if (iou > IOU_THR) bits |= (1u << (j - j0));
        }
        myrow[w] = bits;
    }
    __syncthreads();

    // serial greedy pass: warp 0, each lane owns one 32-bit word of suppressed mask
    if (i < 32) {
        unsigned int sup = 0;
        for (int q = 0; q < TOPK; ++q) {
            const unsigned int supw = __shfl_sync(0xFFFFFFFFu, sup, q >> 5);
            const bool kept = (((supw >> (q & 31)) & 1u) == 0) && (svalid[q] != 0);
            if (i == 0) skeep[q] = kept ? 1 : 0;
            if (kept) sup |= smask[(size_t)q * 32 + i];
        }
    }
    __syncthreads();

    // output: dets = keep ? 8*cand : 0 ; keep as 0/1 float
    const bool kp = (skeep[i] != 0);
    const float f = kp ? STRIDE_S : 0.0f;
    float* od = out + ((size_t)b * TOPK + i) * 7;
    od[0] = f * c0; od[1] = f * c1; od[2] = f * c2; od[3] = f * c3;
    od[4] = f * c4; od[5] = f * c5; od[6] = f * c6;
    out[(size_t)B_IMGS * TOPK * 7 + (size_t)b * TOPK + i] = kp ? 1.0f : 0.0f;
}

// ================= launcher =================
extern "C" void kernel_launch(void* const* d_in, const int* in_sizes, int n_in,
                              void* d_out, int out_size) {
    const float* in = (const float*)d_in[0];
    float* out = (float*)d_out;

    cudaFuncSetAttribute(sort_kernel, cudaFuncAttributeMaxDynamicSharedMemorySize,
                         NSORT * sizeof(unsigned long long));
    cudaFuncSetAttribute(nms_kernel, cudaFuncAttributeMaxDynamicSharedMemorySize,
                         NMS_SMEM);

    decode_kernel<<<dim3(NDET / 256, B_IMGS), 256>>>(in);
    sort_kernel<<<B_IMGS, 1024, NSORT * sizeof(unsigned long long)>>>();
    nms_kernel<<<B_IMGS, 1024, NMS_SMEM>>>(out);
}

// round 3
// speedup vs baseline: 1.5693x; 1.5693x over previous
#include <cuda_runtime.h>
#include <cuda_bf16.h>
#include <cstdint>

// Problem constants (fixed shapes for this problem instance)
#define B_IMGS   32
#define GRID     64
#define NCELL    (GRID * GRID)          // 4096
#define NDET     (NCELL * 3)            // 12288 detections per image
#define NCLS     80
#define TOPK     1024
#define NS2      2048                   // compacted sort size
#define CNF_THR  0.5f
#define IOU_THR  0.4f
#define CLS_OFF  10000.0f
#define STRIDE_S 8.0f                   // HEIGHT/G = 512/64

#define PL ((size_t)B_IMGS * NDET)      // plane stride for SoA det storage

// ---------------- device scratch (static, no runtime allocation) ----------------
// SoA: plane p at g_det[p*PL + b*NDET + l], l = anchor*4096 + s (s = g1*64+g2 linear)
__device__ float               g_det[7 * (size_t)B_IMGS * NDET];   // ~11 MB
__device__ unsigned long long  g_keys[(size_t)B_IMGS * NDET];      // ~3 MB

// order-preserving float->uint mapping
__device__ __forceinline__ unsigned int ord_f32(float f) {
    unsigned int u = __float_as_uint(f);
    return (u & 0x80000000u) ? ~u : (u | 0x80000000u);
}

// ================= Kernel 1: decode (float4, fully coalesced) =================
// thread handles 4 consecutive spatial cells of one anchor. 3072 threads/image.
__global__ void __launch_bounds__(256) decode_kernel(const float* __restrict__ in) {
    const int b   = blockIdx.y;
    const int t4i = blockIdx.x * blockDim.x + threadIdx.x;   // 0..3071
    const int a   = t4i >> 10;                                // anchor 0..2
    const int s0  = (t4i & 1023) << 2;                        // spatial base (mult of 4)

    const float* p = in + ((size_t)b * 255 + (size_t)a * 85) * NCELL + s0;

    const float4 t0 = *(const float4*)(p + 0 * NCELL);
    const float4 t1 = *(const float4*)(p + 1 * NCELL);
    const float4 t2 = *(const float4*)(p + 2 * NCELL);
    const float4 t3 = *(const float4*)(p + 3 * NCELL);
    const float4 t4 = *(const float4*)(p + 4 * NCELL);

    float4 best = *(const float4*)(p + 5 * NCELL);
    int bi0 = 0, bi1 = 0, bi2 = 0, bi3 = 0;
    #pragma unroll 4
    for (int d = 1; d < NCLS; ++d) {
        const float4 v = *(const float4*)(p + (5 + d) * NCELL);
        if (v.x > best.x) { best.x = v.x; bi0 = d; }
        if (v.y > best.y) { best.y = v.y; bi1 = d; }
        if (v.z > best.z) { best.z = v.z; bi2 = d; }
        if (v.w > best.w) { best.w = v.w; bi3 = d; }
    }

    float4 o0, o1, o2, o3, o4, o5, o6;
    unsigned long long keys[4];
    float* px0 = &o0.x; float* px1 = &o1.x; float* px2 = &o2.x; float* px3 = &o3.x;
    float* px4 = &o4.x; float* px5 = &o5.x; float* px6 = &o6.x;
    const float* pt0 = &t0.x; const float* pt1 = &t1.x; const float* pt2 = &t2.x;
    const float* pt3 = &t3.x; const float* pt4 = &t4.x; const float* pb = &best.x;
    const int bis[4] = {bi0, bi1, bi2, bi3};

    #pragma unroll
    for (int e = 0; e < 4; ++e) {
        const int s = s0 + e;
        // detection index in reference order: n = (g2*64+g1)*3 + a, s = g1*64+g2
        const int n = (((s & 63) << 6) | (s >> 6)) * 3 + a;
        const float x_off = (float)((n >> 6) & 63);
        const float y_off = (float)(n & 63);

        const float cx = pt0[e] + x_off;
        const float cy = pt1[e] + y_off;
        const float hw = pt2[e] * 0.5f;
        const float hh = pt3[e] * 0.5f;
        const float conf = 1.0f / (1.0f + expf(-pt4[e]));

        px0[e] = cx - hw;
        px1[e] = cy - hh;
        px2[e] = cx + hw;
        px3[e] = cy + hh;
        px4[e] = conf;
        px5[e] = pb[e];
        px6[e] = (float)bis[e];

        const float score = (conf > CNF_THR) ? conf : (-__int_as_float(0x7f800000));
        keys[e] = ((unsigned long long)ord_f32(score) << 32)
                | (unsigned long long)(0xFFFFFFFFu - (unsigned int)n);
    }

    const size_t l = (size_t)b * NDET + (size_t)a * NCELL + s0;
    *(float4*)(g_det + 0 * PL + l) = o0;
    *(float4*)(g_det + 1 * PL + l) = o1;
    *(float4*)(g_det + 2 * PL + l) = o2;
    *(float4*)(g_det + 3 * PL + l) = o3;
    *(float4*)(g_det + 4 * PL + l) = o4;
    *(float4*)(g_det + 5 * PL + l) = o5;
    *(float4*)(g_det + 6 * PL + l) = o6;
    *(ulonglong2*)(g_keys + l)     = make_ulonglong2(keys[0], keys[1]);
    *(ulonglong2*)(g_keys + l + 2) = make_ulonglong2(keys[2], keys[3]);
}

// ================= Kernel 2: fused select + sort(2048) + NMS + output ==========
// 1 CTA per image, 1024 threads.
// dyn smem layout:
//   u64  skeys[2048]    @0       (16384)
//   uint smask[1024*32] @16384   (131072)
//   f4   sbox[1024]     @147456  (16384)
//   f32  sarea[1024]    @163840  (4096)
//   uint hist[2048]     @167936  (8192)
//   u8   svalid[1024]   @176128  (1024)
//   u8   skeep[1024]    @177152  (1024)
//   uint cnt            @178176  (4)
#define FUSED_SMEM 178432
__global__ void __launch_bounds__(1024) fused_kernel(float* __restrict__ out) {
    extern __shared__ unsigned char smem[];
    unsigned long long* skeys  = (unsigned long long*)(smem);
    unsigned int*       smask  = (unsigned int*)(smem + 16384);
    float4*             sbox   = (float4*)(smem + 147456);
    float*              sarea  = (float*)(smem + 163840);
    unsigned int*       hist   = (unsigned int*)(smem + 167936);
    unsigned char*      svalid = (unsigned char*)(smem + 176128);
    unsigned char*      skeep  = (unsigned char*)(smem + 177152);
    unsigned int*       cnt    = (unsigned int*)(smem + 178176);
    __shared__ unsigned int sT;

    const int b   = blockIdx.x;
    const int tid = threadIdx.x;

    hist[tid] = 0u; hist[tid + 1024] = 0u;
    skeys[tid] = 0ULL; skeys[tid + 1024] = 0ULL;
    if (tid == 0) *cnt = 0u;
    __syncthreads();

    // load all keys for this image into registers, histogram high bits
    unsigned long long kreg[12];
    #pragma unroll
    for (int k = 0; k < 12; ++k) {
        kreg[k] = g_keys[(size_t)b * NDET + tid + k * 1024];
        const unsigned int hi = (unsigned int)(kreg[k] >> 32);
        if (hi >= 0xBF000000u)   // valid (conf > 0.5): ord in (0xBF000000, 0xBF800000)
            atomicAdd(&hist[(hi - 0xBF000000u) >> 12], 1u);
    }
    __syncthreads();

    // inclusive suffix sum over 2048 bins (Hillis-Steele)
    for (int st = 1; st < 2048; st <<= 1) {
        const unsigned int v0 = hist[tid] + ((tid + st < 2048) ? hist[tid + st] : 0u);
        const unsigned int v1 = hist[tid + 1024] + ((tid + 1024 + st < 2048) ? hist[tid + 1024 + st] : 0u);
        __syncthreads();
        hist[tid] = v0; hist[tid + 1024] = v1;
        __syncthreads();
    }

    // threshold bin T: largest bin with suffix >= TOPK (or 0 if fewer than TOPK valid)
    if (tid == 0 && hist[0] < TOPK) sT = 0;
    #pragma unroll
    for (int q = 0; q < 2; ++q) {
        const int bb = tid + q * 1024;
        const unsigned int sfx = hist[bb];
        const unsigned int nxt = (bb + 1 < 2048) ? hist[bb + 1] : 0u;
        if (sfx >= TOPK && nxt < TOPK) sT = (unsigned int)bb;
    }
    __syncthreads();
    const unsigned int T = sT;

    // compact keys with bin >= T into skeys (order fixed by the sort below)
    #pragma unroll
    for (int k = 0; k < 12; ++k) {
        const unsigned int hi = (unsigned int)(kreg[k] >> 32);
        if (hi >= 0xBF000000u && ((hi - 0xBF000000u) >> 12) >= T) {
            const unsigned int pos = atomicAdd(cnt, 1u);
            if (pos < NS2) skeys[pos] = kreg[k];
        }
    }
    __syncthreads();

    // bitonic sort NS2=2048 descending (exact 64-bit keys -> exact top-k order)
    for (int k = 2; k <= NS2; k <<= 1) {
        for (int j = k >> 1; j > 0; j >>= 1) {
            #pragma unroll
            for (int base = 0; base < NS2; base += 1024) {
                const int i = base + tid;
                const int ixj = i ^ j;
                if (ixj > i) {
                    const unsigned long long va = skeys[i];
                    const unsigned long long vb = skeys[ixj];
                    const bool desc = ((i & k) == 0);
                    if (desc ? (va < vb) : (va > vb)) { skeys[i] = vb; skeys[ixj] = va; }
                }
            }
            __syncthreads();
        }
    }

    // ---- NMS on top 1024 ----
    const unsigned long long key = skeys[tid];
    const bool valid = (key != 0ULL);
    float c0 = 0.f, c1 = 0.f, c2 = 0.f, c3 = 0.f, c4 = 0.f, c5 = 0.f, c6 = 0.f;
    if (valid) {
        const unsigned int n = 0xFFFFFFFFu - (unsigned int)(key & 0xFFFFFFFFull);
        const unsigned int r = n / 3u;
        const unsigned int a = n - r * 3u;
        const unsigned int s = ((r & 63u) << 6) | (r >> 6);
        const size_t base = (size_t)b * NDET + (size_t)a * NCELL + s;
        c0 = g_det[0 * PL + base]; c1 = g_det[1 * PL + base];
        c2 = g_det[2 * PL + base]; c3 = g_det[3 * PL + base];
        c4 = g_det[4 * PL + base]; c5 = g_det[5 * PL + base];
        c6 = g_det[6 * PL + base];
    }

    const float sh = c6 * CLS_OFF;
    float4 bx;
    bx.x = c0 + sh; bx.y = c1 + sh; bx.z = c2 + sh; bx.w = c3 + sh;

    sbox[tid]   = bx;
    sarea[tid]  = (c2 - c0) * (c3 - c1);
    svalid[tid] = valid ? 1 : 0;
    __syncthreads();

    // build upper-triangular suppression mask row tid (j > tid only)
    const float myArea = sarea[tid];
    unsigned int* myrow = smask + (size_t)tid * 32;
    for (int w = 0; w < 32; ++w) {
        unsigned int bits = 0;
        const int j0 = w << 5;
        const int jlo = (j0 > tid + 1) ? j0 : (tid + 1);
        const int jhi = j0 + 32;
        for (int j = jlo; j < jhi; ++j) {
            const float4 ob = sbox[j];
            const float lx = fmaxf(bx.x, ob.x);
            const float ly = fmaxf(bx.y, ob.y);
            const float rx = fminf(bx.z, ob.z);
            const float ry = fminf(bx.w, ob.w);
            const float iw = fmaxf(rx - lx, 0.0f);
            const float ih = fmaxf(ry - ly, 0.0f);
            const float inter = iw * ih;
            const float iou = inter / (myArea + sarea[j] - inter + 1e-9f);
            if (iou > IOU_THR) bits |= (1u << (j - j0));
        }
        myrow[w] = bits;
    }
    __syncthreads();

    // serial greedy pass: warp 0, lane i owns suppressed-mask word i
    if (tid < 32) {
        unsigned int sup = 0;
        for (int q = 0; q < TOPK; ++q) {
            const unsigned int supw = __shfl_sync(0xFFFFFFFFu, sup, q >> 5);
            const bool kept = (((supw >> (q & 31)) & 1u) == 0) && (svalid[q] != 0);
            if (tid == 0) skeep[q] = kept ? 1 : 0;
            if (kept) sup |= smask[(size_t)q * 32 + tid];
        }
    }
    __syncthreads();

    // output: dets = keep ? 8*cand : 0 ; keep as 0/1 float
    const bool kp = (skeep[tid] != 0);
    const float f = kp ? STRIDE_S : 0.0f;
    float* od = out + ((size_t)b * TOPK + tid) * 7;
    od[0] = f * c0; od[1] = f * c1; od[2] = f * c2; od[3] = f * c3;
    od[4] = f * c4; od[5] = f * c5; od[6] = f * c6;
    out[(size_t)B_IMGS * TOPK * 7 + (size_t)b * TOPK + tid] = kp ? 1.0f : 0.0f;
}

// ================= launcher =================
extern "C" void kernel_launch(void* const* d_in, const int* in_sizes, int n_in,
                              void* d_out, int out_size) {
    const float* in = (const float*)d_in[0];
    float* out = (float*)d_out;

    cudaFuncSetAttribute(fused_kernel, cudaFuncAttributeMaxDynamicSharedMemorySize,
                         FUSED_SMEM);

    decode_kernel<<<dim3(12, B_IMGS), 256>>>(in);
    fused_kernel<<<B_IMGS, 1024, FUSED_SMEM>>>(out);
}